// round 9
// baseline (speedup 1.0000x reference)
#include <cuda_runtime.h>

// Problem dims (fixed by reference)
#define B 16
#define S 4096
#define D 1024      // D_IN = H = D_OUT = 1024
#define NCHUNK 64
#define SCHUNK (S / NCHUNK)   // 64
#define KSPLIT 8
#define KCHUNK (D / KSPLIT)   // 128
#define R_GRID 512            // K1 blocks; each handles 2 of the 1024 tasks
#define T_GRID 1024           // tail kernel blocks (ALL must be co-resident)

// Scratch (no device allocs allowed)
__device__ float g_part[B * NCHUNK * D];   // 4 MB
__device__ float g_m[B * D];
__device__ float g_enc[B * D];
__device__ unsigned g_bar[2];              // zero-init, monotonic across launches

// ---------------------------------------------------------------------------
// K1: partial sums over S-chunks. grid R_GRID, block 256, 2 tasks per block.
__global__ void reduce_partial_kernel(const float* __restrict__ x,
                                      float* __restrict__ part) {
    const int tid = threadIdx.x;  // 0..255

    #pragma unroll
    for (int t = 0; t < 2; t++) {
        const int task = blockIdx.x + t * R_GRID;   // 0..1023
        const int b = task >> 6;                    // task / NCHUNK
        const int chunk = task & (NCHUNK - 1);

        const float4* xb = (const float4*)(x + (size_t)b * S * D
                                             + (size_t)chunk * SCHUNK * D);

        float4 acc0 = make_float4(0.f, 0.f, 0.f, 0.f);
        float4 acc1 = make_float4(0.f, 0.f, 0.f, 0.f);
        float4 acc2 = make_float4(0.f, 0.f, 0.f, 0.f);
        float4 acc3 = make_float4(0.f, 0.f, 0.f, 0.f);

        #pragma unroll 4
        for (int s = 0; s < SCHUNK; s += 4) {
            float4 v0 = __ldcs(&xb[(size_t)(s + 0) * (D / 4) + tid]);
            float4 v1 = __ldcs(&xb[(size_t)(s + 1) * (D / 4) + tid]);
            float4 v2 = __ldcs(&xb[(size_t)(s + 2) * (D / 4) + tid]);
            float4 v3 = __ldcs(&xb[(size_t)(s + 3) * (D / 4) + tid]);
            acc0.x += v0.x; acc0.y += v0.y; acc0.z += v0.z; acc0.w += v0.w;
            acc1.x += v1.x; acc1.y += v1.y; acc1.z += v1.z; acc1.w += v1.w;
            acc2.x += v2.x; acc2.y += v2.y; acc2.z += v2.z; acc2.w += v2.w;
            acc3.x += v3.x; acc3.y += v3.y; acc3.z += v3.z; acc3.w += v3.w;
        }

        float4 acc;
        acc.x = (acc0.x + acc1.x) + (acc2.x + acc3.x);
        acc.y = (acc0.y + acc1.y) + (acc2.y + acc3.y);
        acc.z = (acc0.z + acc1.z) + (acc2.z + acc3.z);
        acc.w = (acc0.w + acc1.w) + (acc2.w + acc3.w);

        float4* p = (float4*)(part + ((size_t)b * NCHUNK + chunk) * D);
        p[tid] = acc;
    }
}

// ---------------------------------------------------------------------------
// Software grid barrier. Valid because all T_GRID blocks are co-resident
// (launch_bounds(256,8): 8 blocks/SM capacity * 148 SM = 1184 >= 1024).
// Monotonic counter: each launch adds exactly T_GRID per barrier, so the
// per-generation target is consistent across graph replays. Work is
// identical every call (deterministic).
__device__ __forceinline__ void grid_barrier(int k) {
    __syncthreads();
    if (threadIdx.x == 0) {
        __threadfence();                       // publish my writes/atomics
        unsigned old = atomicAdd(&g_bar[k], 1u);
        unsigned target = (old / T_GRID + 1u) * T_GRID;
        while (*((volatile unsigned*)&g_bar[k]) < target) {
            __nanosleep(64);
        }
        __threadfence();                       // acquire others' writes
    }
    __syncthreads();
}

// ---------------------------------------------------------------------------
// gemv phase body: split-K batched GEMV, one (n, K-chunk) per warp.
// blk -> bx = blk>>3 (n-group), kc = blk&7 (K-chunk). W float4 'w' is
// preloaded by the caller (hoisted above the barrier for latency overlap).
__device__ __forceinline__ void gemv_phase(const float* __restrict__ vin,
                                           const float4 w,
                                           float* __restrict__ vout,
                                           float4* sh,
                                           int blk, int warp, int lane) {
    const int K0 = (blk & (KSPLIT - 1)) * KCHUNK;
    const int n = (blk >> 3) * 8 + warp;

    // Cooperative tile fill: vin[:, K0:K0+128] -> 8 KB smem.
    {
        const float4* v4 = (const float4*)vin;
        sh[warp * 32 + lane]       = v4[(size_t)warp * (D / 4)       + K0 / 4 + lane];
        sh[(warp + 8) * 32 + lane] = v4[(size_t)(warp + 8) * (D / 4) + K0 / 4 + lane];
    }
    __syncthreads();

    float acc[B];
    #pragma unroll
    for (int b = 0; b < B; b++) {
        float4 v = sh[b * 32 + lane];
        acc[b] = ((w.x * v.x + w.y * v.y) + (w.z * v.z + w.w * v.w));
    }

    // Interleaved pairwise reduction: 16 SHFLs; lane l ends with b = l & 15.
    float u8[8];
    #pragma unroll
    for (int j = 0; j < 8; j++) {
        float mine  = (lane & 1) ? acc[2 * j + 1] : acc[2 * j];
        float other = (lane & 1) ? acc[2 * j]     : acc[2 * j + 1];
        u8[j] = mine + __shfl_xor_sync(0xFFFFFFFFu, other, 1);
    }
    float u4[4];
    #pragma unroll
    for (int j = 0; j < 4; j++) {
        float mine  = (lane & 2) ? u8[2 * j + 1] : u8[2 * j];
        float other = (lane & 2) ? u8[2 * j]     : u8[2 * j + 1];
        u4[j] = mine + __shfl_xor_sync(0xFFFFFFFFu, other, 2);
    }
    float u2[2];
    #pragma unroll
    for (int j = 0; j < 2; j++) {
        float mine  = (lane & 4) ? u4[2 * j + 1] : u4[2 * j];
        float other = (lane & 4) ? u4[2 * j]     : u4[2 * j + 1];
        u2[j] = mine + __shfl_xor_sync(0xFFFFFFFFu, other, 4);
    }
    float mine  = (lane & 8) ? u2[1] : u2[0];
    float other = (lane & 8) ? u2[0] : u2[1];
    float u = mine + __shfl_xor_sync(0xFFFFFFFFu, other, 8);
    u += __shfl_xor_sync(0xFFFFFFFFu, u, 16);

    if (lane < B)
        atomicAdd(&vout[(size_t)lane * D + n], u);
}

// ---------------------------------------------------------------------------
// Fused tail: combine -> barrier -> gemv1 -> barrier -> gemv2.
__global__ void __launch_bounds__(256, 8)
tail_kernel(const float* __restrict__ part,
            const float* __restrict__ W_enc,
            const float* __restrict__ b_enc,
            const float* __restrict__ W_out,
            const float* __restrict__ b_out,
            float* __restrict__ m,
            float* __restrict__ enc,
            float* __restrict__ out) {
    __shared__ float4 sh[B * (KCHUNK / 4)];   // 8 KB, reused by both phases

    const int tid = threadIdx.x;
    const int blk = blockIdx.x;
    const int warp = tid >> 5;
    const int lane = tid & 31;

    // Hoisted W loads for BOTH layers: their DRAM latency overlaps phase 0,
    // the barriers, and (for w2) all of phase 1.
    const int K0 = (blk & (KSPLIT - 1)) * KCHUNK;
    const int n = (blk >> 3) * 8 + warp;
    const float4 w1 = __ldg(&((const float4*)(W_enc + (size_t)n * D + K0))[lane]);
    const float4 w2 = __ldg(&((const float4*)(W_out + (size_t)n * D + K0))[lane]);

    // ---- Phase 0: combine (mean) + bias pre-init of enc/out ----
    // Each warp handles 2 elements; 16 lanes cooperate per element
    // (each lane sums 4 of the 64 chunk partials), half-warp shfl reduce.
    {
        const int e = blk * 16 + warp * 2 + (lane >> 4);  // 0 .. B*D-1
        const int g = lane & 15;
        const int eb = e >> 10;
        const int ed = e & (D - 1);
        const float* p = part + (size_t)eb * NCHUNK * D + ed;
        float s = 0.f;
        #pragma unroll
        for (int c = 0; c < 4; c++)
            s += p[(size_t)(g * 4 + c) * D];
        #pragma unroll
        for (int o = 8; o; o >>= 1)
            s += __shfl_xor_sync(0xFFFFFFFFu, s, o);
        if (g == 0) {
            m[e]   = s * (1.0f / (float)S);
            enc[e] = b_enc[ed];
            out[e] = b_out[ed];
        }
    }

    grid_barrier(0);

    // ---- Phase 1: enc += m @ W_enc.T (split-K, atomic commit) ----
    gemv_phase(m, w1, enc, sh, blk, warp, lane);

    grid_barrier(1);

    // ---- Phase 2: out += enc @ W_out.T ----
    gemv_phase(enc, w2, out, sh, blk, warp, lane);
}

extern "C" void kernel_launch(void* const* d_in, const int* in_sizes, int n_in,
                              void* d_out, int out_size) {
    const float* x     = (const float*)d_in[0];
    const float* W_enc = (const float*)d_in[1];
    const float* b_enc = (const float*)d_in[2];
    const float* W_out = (const float*)d_in[3];
    const float* b_out = (const float*)d_in[4];
    float* out = (float*)d_out;

    float* part; cudaGetSymbolAddress((void**)&part, g_part);
    float* m;    cudaGetSymbolAddress((void**)&m,    g_m);
    float* enc;  cudaGetSymbolAddress((void**)&enc,  g_enc);

    reduce_partial_kernel<<<R_GRID, 256>>>(x, part);
    tail_kernel<<<T_GRID, 256>>>(part, W_enc, b_enc, W_out, b_out, m, enc, out);
}

// round 10
// speedup vs baseline: 1.1750x; 1.1750x over previous
#include <cuda_runtime.h>

// Problem dims (fixed by reference)
#define B 16
#define S 4096
#define D 1024      // D_IN = H = D_OUT = 1024
#define NCHUNK 64
#define SCHUNK (S / NCHUNK)   // 64
#define KSPLIT 8
#define KCHUNK (D / KSPLIT)   // 128
#define R_GRID 512            // K1 blocks; each handles 2 of the 1024 tasks

// Scratch (no device allocs allowed)
__device__ float g_part[B * NCHUNK * D];   // 4 MB
__device__ float g_m[B * D];
__device__ float g_enc[B * D];

// ---------------------------------------------------------------------------
// K1: partial sums over S-chunks. grid R_GRID, block 256, 2 tasks per block.
// 8 LDG.128 batched per iteration -> ~224 lines in flight per SM (need ~192
// to cover DRAM latency at the per-SM bandwidth share).
__global__ void reduce_partial_kernel(const float* __restrict__ x,
                                      float* __restrict__ part) {
    const int tid = threadIdx.x;  // 0..255

    #pragma unroll
    for (int t = 0; t < 2; t++) {
        const int task = blockIdx.x + t * R_GRID;   // 0..1023
        const int b = task >> 6;                    // task / NCHUNK
        const int chunk = task & (NCHUNK - 1);

        const float4* xb = (const float4*)(x + (size_t)b * S * D
                                             + (size_t)chunk * SCHUNK * D);

        float4 acc0 = make_float4(0.f, 0.f, 0.f, 0.f);
        float4 acc1 = make_float4(0.f, 0.f, 0.f, 0.f);
        float4 acc2 = make_float4(0.f, 0.f, 0.f, 0.f);
        float4 acc3 = make_float4(0.f, 0.f, 0.f, 0.f);

        #pragma unroll 2
        for (int s = 0; s < SCHUNK; s += 8) {
            float4 v[8];
            #pragma unroll
            for (int j = 0; j < 8; j++)
                v[j] = __ldcs(&xb[(size_t)(s + j) * (D / 4) + tid]);
            #pragma unroll
            for (int j = 0; j < 8; j += 4) {
                acc0.x += v[j].x;   acc0.y += v[j].y;   acc0.z += v[j].z;   acc0.w += v[j].w;
                acc1.x += v[j+1].x; acc1.y += v[j+1].y; acc1.z += v[j+1].z; acc1.w += v[j+1].w;
                acc2.x += v[j+2].x; acc2.y += v[j+2].y; acc2.z += v[j+2].z; acc2.w += v[j+2].w;
                acc3.x += v[j+3].x; acc3.y += v[j+3].y; acc3.z += v[j+3].z; acc3.w += v[j+3].w;
            }
        }

        float4 acc;
        acc.x = (acc0.x + acc1.x) + (acc2.x + acc3.x);
        acc.y = (acc0.y + acc1.y) + (acc2.y + acc3.y);
        acc.z = (acc0.z + acc1.z) + (acc2.z + acc3.z);
        acc.w = (acc0.w + acc1.w) + (acc2.w + acc3.w);

        float4* p = (float4*)(part + ((size_t)b * NCHUNK + chunk) * D);
        p[tid] = acc;
    }
}

// ---------------------------------------------------------------------------
// K2: combine partials -> mean, pre-init enc/out with biases.
// PDL: bias prologue runs while K1 is still executing; part reads wait.
__global__ void combine_kernel(const float* __restrict__ part,
                               float* __restrict__ m,
                               const float* __restrict__ b_enc,
                               float* __restrict__ enc,
                               const float* __restrict__ b_out,
                               float* __restrict__ out) {
    const int i = blockIdx.x * blockDim.x + threadIdx.x;  // 0 .. B*D-1
    const int d = i & (D - 1);

    // Independent prologue (inputs, not touched by K1).
    const float be = b_enc[d];
    const float bo = b_out[d];

    cudaGridDependencySynchronize();   // wait for K1's partials

    const int b = i >> 10;
    float s = 0.f;
    #pragma unroll
    for (int c = 0; c < NCHUNK; c++)
        s += part[((size_t)b * NCHUNK + c) * D + d];
    m[i] = s * (1.0f / (float)S);
    enc[i] = be;
    out[i] = bo;
}

// ---------------------------------------------------------------------------
// K3/K4: split-K batched GEMV with smem-staged activations.
// PDL: the W row LDG (pure input) issues while the predecessor kernel is
// still running; everything touching vin/vout waits at the dependency sync.
__global__ void __launch_bounds__(256)
gemv_split_kernel(const float* __restrict__ vin,   // [B, D]
                  const float* __restrict__ W,     // [D, D]
                  float* __restrict__ vout) {      // [B, D] (+=)
    __shared__ float4 sh[B * (KCHUNK / 4)];   // 16 x 32 float4 = 8 KB

    const int K0 = blockIdx.y * KCHUNK;
    const int warp = threadIdx.x >> 5;
    const int lane = threadIdx.x & 31;
    const int n = blockIdx.x * 8 + warp;

    // Prologue: W row load overlaps the predecessor's tail + our ramp.
    const float4 w = __ldg(&((const float4*)(W + (size_t)n * D + K0))[lane]);

    cudaGridDependencySynchronize();   // vin/vout now valid

    // Cooperative fill: vin[:, K0:K0+128] -> 8 KB smem.
    {
        const float4* v4 = (const float4*)vin;
        sh[warp * 32 + lane]       = v4[(size_t)warp * (D / 4)       + K0 / 4 + lane];
        sh[(warp + 8) * 32 + lane] = v4[(size_t)(warp + 8) * (D / 4) + K0 / 4 + lane];
    }
    __syncthreads();

    float acc[B];
    #pragma unroll
    for (int b = 0; b < B; b++) {
        float4 v = sh[b * 32 + lane];
        acc[b] = ((w.x * v.x + w.y * v.y) + (w.z * v.z + w.w * v.w));
    }

    // Interleaved pairwise reduction: 16 SHFLs; lane l ends with b = l & 15.
    float u8[8];
    #pragma unroll
    for (int j = 0; j < 8; j++) {
        float mine  = (lane & 1) ? acc[2 * j + 1] : acc[2 * j];
        float other = (lane & 1) ? acc[2 * j]     : acc[2 * j + 1];
        u8[j] = mine + __shfl_xor_sync(0xFFFFFFFFu, other, 1);
    }
    float u4[4];
    #pragma unroll
    for (int j = 0; j < 4; j++) {
        float mine  = (lane & 2) ? u8[2 * j + 1] : u8[2 * j];
        float other = (lane & 2) ? u8[2 * j]     : u8[2 * j + 1];
        u4[j] = mine + __shfl_xor_sync(0xFFFFFFFFu, other, 2);
    }
    float u2[2];
    #pragma unroll
    for (int j = 0; j < 2; j++) {
        float mine  = (lane & 4) ? u4[2 * j + 1] : u4[2 * j];
        float other = (lane & 4) ? u4[2 * j]     : u4[2 * j + 1];
        u2[j] = mine + __shfl_xor_sync(0xFFFFFFFFu, other, 4);
    }
    float mine  = (lane & 8) ? u2[1] : u2[0];
    float other = (lane & 8) ? u2[0] : u2[1];
    float u = mine + __shfl_xor_sync(0xFFFFFFFFu, other, 8);
    u += __shfl_xor_sync(0xFFFFFFFFu, u, 16);

    if (lane < B)
        atomicAdd(&vout[(size_t)lane * D + n], u);
}

// ---------------------------------------------------------------------------
extern "C" void kernel_launch(void* const* d_in, const int* in_sizes, int n_in,
                              void* d_out, int out_size) {
    const float* x     = (const float*)d_in[0];
    const float* W_enc = (const float*)d_in[1];
    const float* b_enc = (const float*)d_in[2];
    const float* W_out = (const float*)d_in[3];
    const float* b_out = (const float*)d_in[4];
    float* out = (float*)d_out;

    float* part; cudaGetSymbolAddress((void**)&part, g_part);
    float* m;    cudaGetSymbolAddress((void**)&m,    g_m);
    float* enc;  cudaGetSymbolAddress((void**)&enc,  g_enc);

    // K1: normal launch.
    reduce_partial_kernel<<<R_GRID, 256>>>(x, part);

    // Tail kernels: PDL so each overlaps the predecessor's tail/ramp.
    cudaLaunchAttribute attr[1];
    attr[0].id = cudaLaunchAttributeProgrammaticStreamSerialization;
    attr[0].val.programmaticStreamSerializationAllowed = 1;

    {
        cudaLaunchConfig_t cfg = {};
        cfg.gridDim = dim3((B * D) / 256);
        cfg.blockDim = dim3(256);
        cfg.stream = 0;
        cfg.attrs = attr;
        cfg.numAttrs = 1;
        cudaLaunchKernelEx(&cfg, combine_kernel,
                           (const float*)part, m, b_enc, enc, b_out, out);
    }
    {
        cudaLaunchConfig_t cfg = {};
        cfg.gridDim = dim3(D / 8, KSPLIT);
        cfg.blockDim = dim3(256);
        cfg.stream = 0;
        cfg.attrs = attr;
        cfg.numAttrs = 1;
        cudaLaunchKernelEx(&cfg, gemv_split_kernel,
                           (const float*)m, W_enc, enc);
    }
    {
        cudaLaunchConfig_t cfg = {};
        cfg.gridDim = dim3(D / 8, KSPLIT);
        cfg.blockDim = dim3(256);
        cfg.stream = 0;
        cfg.attrs = attr;
        cfg.numAttrs = 1;
        cudaLaunchKernelEx(&cfg, gemv_split_kernel,
                           (const float*)enc, W_out, out);
    }
}